// round 6
// baseline (speedup 1.0000x reference)
#include <cuda_runtime.h>
#include <cuda_fp16.h>
#include <cstdint>

#define HH 256
#define WW 256
#define NB 8
#define PLANE (HH*WW)
#define CIN 256
#define CHID 16

// per-sample demodulated conv weights, fp16 half2-packed, dense:
// [b][tap][o][32 words]  (word ip = channels 2ip, 2ip+1)
__device__ unsigned g_wmodh[NB * 9 * 64 * 32];

// ---------------------------------------------------------------------------
// Kernel 1: style MLP + weight modulation/demodulation -> fp16 packed weights
// ---------------------------------------------------------------------------
__global__ void style_kernel(const float* __restrict__ vec,
                             const float* __restrict__ w1,
                             const float* __restrict__ w2,
                             const float* __restrict__ wconv) {
    const int b = blockIdx.x, tid = threadIdx.x;
    __shared__ float sv[CIN], sh[CHID], ss[64];
    sv[tid] = vec[b*CIN + tid];
    __syncthreads();
    if (tid < CHID) {
        float acc = 0.f;
        #pragma unroll 8
        for (int c = 0; c < CIN; ++c) acc += sv[c] * w1[tid*CIN + c];
        sh[tid] = (acc > 0.f) ? acc : 0.1f * acc;     // LeakyReLU(0.1)
    }
    __syncthreads();
    if (tid < 64) {
        float acc = 0.f;
        #pragma unroll
        for (int j = 0; j < CHID; ++j) acc += sh[j] * w2[tid*CHID + j];
        ss[tid] = acc + 1.0f;                          // sty + 1
    }
    __syncthreads();
    const int warp = tid >> 5, lane = tid & 31;
    for (int o = warp; o < 64; o += 8) {
        float acc = 0.f;
        for (int idx = lane; idx < 576; idx += 32) {
            float v = wconv[o*576 + idx] * ss[idx / 9];
            acc += v * v;
        }
        #pragma unroll
        for (int s = 16; s; s >>= 1) acc += __shfl_xor_sync(0xffffffffu, acc, s);
        const float d = rsqrtf(acc + 1e-8f);
        for (int m = lane; m < 288; m += 32) {
            const int ip = m / 9, t = m % 9;
            const int i0 = 2 * ip;
            float v0 = wconv[o*576 + i0*9 + t]     * ss[i0]   * d;
            float v1 = wconv[o*576 + (i0+1)*9 + t] * ss[i0+1] * d;
            __half2 h = __floats2half2_rn(v0, v1);
            g_wmodh[(size_t)((b*9 + t)*64 + o)*32 + ip] = *(unsigned*)&h;
        }
    }
}

// ---------------------------------------------------------------------------
// Kernel 2: fused ChanNorm + 3x3 modulated conv (fp16 m16n8k16, ldmatrix) + res
// CTA = 4 image rows x 64 cols x 64 out-ch; 4 warps, warp = one image row,
// warp tile Mw=64 px, Nw=64 ch (acc[4][8][4] = 128 regs).  2 CTAs/SM.
// xs: [pix = r*66+cc][36 words] half2; wt: double buffer [2][64][36 words].
// Stride 36 words = 9x16B: ldmatrix 8-row fetch conflict-free (9i mod 8 = i).
// ---------------------------------------------------------------------------
#define XW 36
#define HROWS 6
#define HCOLS 66
#define NPX (HROWS*HCOLS)                 /* 396 halo pixels */
#define OFF_WT (NPX*XW)                   /* 14256 words */
#define WTBUF  (64*XW)                    /* 2304 words per buffer */
#define OFF_G  (OFF_WT + 2*WTBUF)
#define OFF_B  (OFF_G + 64)
#define SMEM_WORDS (OFF_B + 64)           /* 18992 words = 75968 B */

__device__ __forceinline__ uint32_t smem_u32(const void* p) {
    uint32_t a;
    asm("{ .reg .u64 t; cvta.to.shared.u64 t, %1; cvt.u32.u64 %0, t; }" : "=r"(a) : "l"(p));
    return a;
}
__device__ __forceinline__ void ldsm_x4(unsigned r[4], uint32_t addr) {
    asm volatile("ldmatrix.sync.aligned.m8n8.x4.shared.b16 {%0,%1,%2,%3}, [%4];"
        : "=r"(r[0]), "=r"(r[1]), "=r"(r[2]), "=r"(r[3]) : "r"(addr));
}
__device__ __forceinline__ void mma_f16(float c[4],
                                        unsigned a0, unsigned a1,
                                        unsigned a2, unsigned a3,
                                        unsigned b0, unsigned b1) {
    asm volatile(
        "mma.sync.aligned.m16n8k16.row.col.f32.f16.f16.f32 "
        "{%0,%1,%2,%3}, {%4,%5,%6,%7}, {%8,%9}, {%0,%1,%2,%3};\n"
        : "+f"(c[0]), "+f"(c[1]), "+f"(c[2]), "+f"(c[3])
        : "r"(a0), "r"(a1), "r"(a2), "r"(a3), "r"(b0), "r"(b1));
}

__global__ __launch_bounds__(128, 2)
void conv_kernel(const float* __restrict__ x,
                 const float* __restrict__ gaff,
                 const float* __restrict__ baff,
                 float* __restrict__ out) {
    extern __shared__ unsigned sm[];
    unsigned* xs = sm;
    float* sg = (float*)(sm + OFF_G);
    float* sb = (float*)(sm + OFF_B);

    const int tid = threadIdx.x, warp = tid >> 5, lane = tid & 31;
    const int gq = lane >> 2, tq = lane & 3;
    const int x0 = blockIdx.x * 64, y0 = blockIdx.y * 4, b = blockIdx.z;
    const float* xb = x + (size_t)b * 64 * PLANE;

    if (tid < 64) { sg[tid] = gaff[tid]; sb[tid] = baff[tid]; }
    __syncthreads();

    // ---- ChanNorm halo tile -> fp16 half2 smem ----
    for (int p = tid; p < NPX; p += 128) {
        const int r = p / HCOLS, cc = p % HCOLS;
        const int gy = y0 - 1 + r, gx = x0 - 1 + cc;
        uint4* dst = (uint4*)(xs + p * XW);
        if (gy >= 0 && gy < HH && gx >= 0 && gx < WW) {
            const float* px = xb + (size_t)gy * WW + gx;
            float v[64], s = 0.f, s2 = 0.f;
            #pragma unroll
            for (int c = 0; c < 64; ++c) v[c] = px[(size_t)c * PLANE];
            #pragma unroll
            for (int c = 0; c < 64; ++c) { s += v[c]; s2 += v[c]*v[c]; }
            const float mean = s * (1.f/64.f);
            const float rstd = rsqrtf(s2 * (1.f/64.f) - mean*mean + 1e-5f);
            #pragma unroll
            for (int u = 0; u < 8; ++u) {
                uint4 w;
                unsigned* wp = (unsigned*)&w;
                #pragma unroll
                for (int q = 0; q < 4; ++q) {
                    const int c0 = u*8 + q*2;
                    float n0 = (v[c0]   - mean) * rstd * sg[c0]   + sb[c0];
                    float n1 = (v[c0+1] - mean) * rstd * sg[c0+1] + sb[c0+1];
                    __half2 h = __floats2half2_rn(n0, n1);
                    wp[q] = *(unsigned*)&h;
                }
                dst[u] = w;
            }
        } else {
            const uint4 z = {0u,0u,0u,0u};
            #pragma unroll
            for (int u = 0; u < 8; ++u) dst[u] = z;     // pad AFTER norm
        }
    }

    // ---- weight prefetch: tap0 -> wt buf0, tap1 -> regs ----
    const unsigned* wbase = g_wmodh + (size_t)(b * 9) * 2048;
    uint4 wr[4];
    {
        const uint4* s4 = (const uint4*)wbase + tid * 4;
        #pragma unroll
        for (int i = 0; i < 4; ++i) wr[i] = s4[i];
        uint4* d = (uint4*)(sm + OFF_WT + (tid >> 1) * XW + (tid & 1) * 16);
        #pragma unroll
        for (int i = 0; i < 4; ++i) d[i] = wr[i];
        const uint4* s4b = (const uint4*)(wbase + 2048) + tid * 4;
        #pragma unroll
        for (int i = 0; i < 4; ++i) wr[i] = s4b[i];
    }

    // ---- ldmatrix base addresses (byte, shared space) ----
    const uint32_t xs_sa = smem_u32(sm);
    const uint32_t wt_sa = xs_sa + OFF_WT * 4;
    const uint32_t A0 = xs_sa + ((warp * HCOLS + (lane & 15)) * XW) * 4 + (lane >> 4) * 16;
    const uint32_t B0 = wt_sa + (((lane & 7) + ((lane >> 4) & 1) * 8) * XW) * 4
                              + ((lane >> 3) & 1) * 16;

    __syncthreads();                                   // xs + wt0 ready

    float acc[4][8][4];
    #pragma unroll
    for (int mt = 0; mt < 4; ++mt)
        #pragma unroll
        for (int nt = 0; nt < 8; ++nt)
            #pragma unroll
            for (int j = 0; j < 4; ++j) acc[mt][nt][j] = 0.f;

    for (int j = 0; j < 9; ++j) {
        const int ky = j / 3, kx = j % 3, s = j & 1;
        const uint32_t Abase = A0 + (uint32_t)((ky * HCOLS + kx) * XW) * 4;
        const uint32_t Bbase = B0 + (uint32_t)(s * WTBUF) * 4;

        unsigned a[2][4][4], bq[2][4][4];
        #pragma unroll
        for (int mt = 0; mt < 4; ++mt)
            ldsm_x4(a[0][mt], Abase + (uint32_t)(mt * 16 * XW) * 4);
        #pragma unroll
        for (int q = 0; q < 4; ++q)
            ldsm_x4(bq[0][q], Bbase + (uint32_t)(q * 16 * XW) * 4);

        #pragma unroll
        for (int kt = 0; kt < 4; ++kt) {
            const int cur = kt & 1, nxt = cur ^ 1;
            if (kt < 3) {
                const uint32_t ko = (uint32_t)(kt + 1) * 32;
                #pragma unroll
                for (int mt = 0; mt < 4; ++mt)
                    ldsm_x4(a[nxt][mt], Abase + (uint32_t)(mt * 16 * XW) * 4 + ko);
                #pragma unroll
                for (int q = 0; q < 4; ++q)
                    ldsm_x4(bq[nxt][q], Bbase + (uint32_t)(q * 16 * XW) * 4 + ko);
            }
            #pragma unroll
            for (int mt = 0; mt < 4; ++mt) {
                #pragma unroll
                for (int q = 0; q < 4; ++q) {
                    mma_f16(acc[mt][2*q],   a[cur][mt][0], a[cur][mt][1],
                            a[cur][mt][2], a[cur][mt][3],
                            bq[cur][q][0], bq[cur][q][1]);
                    mma_f16(acc[mt][2*q+1], a[cur][mt][0], a[cur][mt][1],
                            a[cur][mt][2], a[cur][mt][3],
                            bq[cur][q][2], bq[cur][q][3]);
                }
            }
        }

        if (j < 8) {
            uint4* d = (uint4*)(sm + OFF_WT + (s ^ 1) * WTBUF
                                + (tid >> 1) * XW + (tid & 1) * 16);
            #pragma unroll
            for (int i = 0; i < 4; ++i) d[i] = wr[i];
            if (j < 7) {
                const uint4* s4 = (const uint4*)(wbase + (size_t)(j+2)*2048) + tid*4;
                #pragma unroll
                for (int i = 0; i < 4; ++i) wr[i] = s4[i];
            }
        }
        __syncthreads();
    }

    // ---- epilogue: stage acc -> smem (per-warp slice), coalesced res+store ----
    __syncthreads();                         // all ldsm reads of xs are done
    float* ss = (float*)(sm) + warp * 2112;  // 32ch x 66 floats per warp
    const int gy = y0 + warp;
    float* ob = out + (size_t)b * 64 * PLANE;

    #pragma unroll
    for (int P = 0; P < 2; ++P) {
        #pragma unroll
        for (int mt = 0; mt < 4; ++mt) {
            const int px = mt*16 + gq;
            #pragma unroll
            for (int ntl = 0; ntl < 4; ++ntl) {
                const int nt = P*4 + ntl;
                const int c = ntl*8 + 2*tq;
                ss[c*66 + px]         = acc[mt][nt][0];
                ss[(c+1)*66 + px]     = acc[mt][nt][1];
                ss[c*66 + px + 8]     = acc[mt][nt][2];
                ss[(c+1)*66 + px + 8] = acc[mt][nt][3];
            }
        }
        __syncwarp();
        #pragma unroll 4
        for (int c = 0; c < 32; ++c) {
            const int cg = P*32 + c;
            const size_t gi = (size_t)cg * PLANE + (size_t)gy * WW + x0 + 2*lane;
            const float2 v = *(const float2*)&ss[c*66 + 2*lane];
            const float2 rx = *(const float2*)&xb[gi];
            float2 o2; o2.x = v.x + rx.x; o2.y = v.y + rx.y;
            *(float2*)&ob[gi] = o2;
        }
        __syncwarp();
    }
}

// ---------------------------------------------------------------------------
extern "C" void kernel_launch(void* const* d_in, const int* in_sizes, int n_in,
                              void* d_out, int out_size) {
    (void)in_sizes; (void)n_in; (void)out_size;
    const float* x     = (const float*)d_in[0];
    const float* vec   = (const float*)d_in[1];
    const float* gaff  = (const float*)d_in[2];
    const float* baff  = (const float*)d_in[3];
    const float* w1    = (const float*)d_in[4];
    const float* w2    = (const float*)d_in[5];
    const float* wconv = (const float*)d_in[6];
    float* out = (float*)d_out;

    style_kernel<<<NB, 256>>>(vec, w1, w2, wconv);

    const int smem = SMEM_WORDS * 4;
    cudaFuncSetAttribute(conv_kernel,
                         cudaFuncAttributeMaxDynamicSharedMemorySize, smem);
    dim3 grid(WW/64, HH/4, NB);
    conv_kernel<<<grid, 128, smem>>>(x, gaff, baff, out);
}